// round 8
// baseline (speedup 1.0000x reference)
#include <cuda_runtime.h>
#include <cstdint>

// EMA scan via decoupled chained scan (exact, single pass, minimal traffic),
// with a bounded-spin + warmup fallback so forward progress never depends on
// block scheduling order (hang-proof version of the round-7 design).
//
// out[b,0,c] = x[b,0,c]; out[b,t,c] = 0.1*x[b,t,c] + 0.9*out[b,t-1,c]
// Shape (16, 4096, 512) fp32.
//
// Block = 1 chunk of 64 timesteps x 256 channels (half of C=512).
// 512 threads = 8 t-segments x 64 float4-channel-groups.
// Linearity: out[t] = local_zeroinit[t] + B^(t+1) * carry_in.
// Chains: 16 batches x 2 halves = 32, each 64 links deep.

namespace {
constexpr int T      = 4096;
constexpr int C4     = 128;             // float4 channel groups (512 ch)
constexpr int SEGS   = 8;
constexpr int PSTEPS = 8;
constexpr int CGB    = 64;              // channel-groups per block
constexpr int CHUNK  = SEGS * PSTEPS;   // 64 timesteps per block
constexpr int NCHUNK = T / CHUNK;       // 64
constexpr int NCHAIN = 16 * 2;          // batches x channel-halves
constexpr float A  = 0.1f;
constexpr float Bc = 0.9f;
constexpr int MAXSPIN = 4096;           // bounded wait -> no hang possible

constexpr float fpow(float b, int n) { float r = 1.0f; for (int i = 0; i < n; ++i) r *= b; return r; }
constexpr float B8  = fpow(Bc, 8);
constexpr float B12 = fpow(Bc, 12);
constexpr float B64 = fpow(Bc, 64);
}

__device__ unsigned g_flags[NCHAIN][NCHUNK];           // zero-init; self-resetting
__device__ float4   g_carry[NCHAIN][NCHUNK][CGB];

__constant__ float B8S[SEGS] = {
    fpow(Bc, 0),  fpow(Bc, 8),  fpow(Bc, 16), fpow(Bc, 24),
    fpow(Bc, 32), fpow(Bc, 40), fpow(Bc, 48), fpow(Bc, 56)
};
__constant__ float BPOW[PSTEPS] = {
    fpow(Bc, 1), fpow(Bc, 2), fpow(Bc, 3), fpow(Bc, 4),
    fpow(Bc, 5), fpow(Bc, 6), fpow(Bc, 7), fpow(Bc, 8)
};

__device__ __forceinline__ float4 fma4(float s, const float4 a, const float4 b) {
    // s*a + b
    float4 r;
    r.x = fmaf(s, a.x, b.x);
    r.y = fmaf(s, a.y, b.y);
    r.z = fmaf(s, a.z, b.z);
    r.w = fmaf(s, a.w, b.w);
    return r;
}

__global__ __launch_bounds__(512, 2) void ema_chain_kernel(
    const float4* __restrict__ x, float4* __restrict__ out)
{
    __shared__ float4  s_segL[SEGS][CGB];
    __shared__ float4  s_pref[SEGS + 1][CGB];
    __shared__ float4  s_cin[CGB];
    __shared__ unsigned s_ok;

    const int tid   = threadIdx.x;
    const int cg    = tid & (CGB - 1);
    const int seg   = tid >> 6;
    const int chain = blockIdx.x;           // 0..31  (b*2 + half)
    const int chunk = blockIdx.y;           // 0..63  (slow dim -> bid order)
    const int b     = chain >> 1;
    const int half  = chain & 1;
    const int cgg   = half * CGB + cg;

    const int    t0    = chunk * CHUNK;
    const int    tbase = t0 + seg * PSTEPS;
    const size_t gbase = ((size_t)b * T + tbase) * C4 + cgg;

    // ---- load 8 timesteps (streaming; each x element read exactly once) ----
    float4 v[PSTEPS];
    const float4* xp = x + gbase;
    #pragma unroll
    for (int i = 0; i < PSTEPS; ++i) v[i] = __ldcs(xp + (size_t)i * C4);

    // ---- zero-init local EMA, in place ----
    const bool first = (chunk == 0 && seg == 0);
    if (!first) { v[0].x *= A; v[0].y *= A; v[0].z *= A; v[0].w *= A; }
    // (global t=0: out[0] = x[0], absorbed into local with carry_in = 0)
    #pragma unroll
    for (int i = 1; i < PSTEPS; ++i) {
        v[i].x = fmaf(Bc, v[i-1].x, A * v[i].x);
        v[i].y = fmaf(Bc, v[i-1].y, A * v[i].y);
        v[i].z = fmaf(Bc, v[i-1].z, A * v[i].z);
        v[i].w = fmaf(Bc, v[i-1].w, A * v[i].w);
    }

    s_segL[seg][cg] = v[PSTEPS - 1];
    __syncthreads();

    // ---- segment prefix compose (seg-0 threads, one per channel-group) ----
    if (seg == 0) {
        float4 c = make_float4(0.f, 0.f, 0.f, 0.f);
        #pragma unroll
        for (int s = 0; s < SEGS; ++s) {
            s_pref[s][cg] = c;
            c = fma4(B8, c, s_segL[s][cg]);   // c = segL + B8*c
        }
        s_pref[SEGS][cg] = c;                 // chunk-local carry-out (zero-init)
    }
    __syncthreads();

    // ---- obtain carry_in: exact (flag chain) or fallback (warmup) ----
    float4 cin = make_float4(0.f, 0.f, 0.f, 0.f);
    if (chunk > 0) {
        if (tid == 0) {
            const unsigned* fp = &g_flags[chain][chunk - 1];
            unsigned f = 0;
            for (int it = 0; it < MAXSPIN; ++it) {
                asm volatile("ld.acquire.gpu.u32 %0, [%1];" : "=r"(f) : "l"(fp) : "memory");
                if (f) break;
                __nanosleep(64);
            }
            s_ok = f;
        }
        __syncthreads();

        if (s_ok) {
            cin = g_carry[chain][chunk - 1][cg];
        } else {
            // Fallback: reconstruct carry from a warmup window (never hangs).
            // W=64 (exact, includes t=0) for chunk 1; W=96 (0.9^96 ~ 4e-5) else.
            const int W_eff = (chunk == 1) ? 64 : 96;
            const int PW    = W_eff / SEGS;              // 8 or 12
            const float cB  = (chunk == 1) ? B8 : B12;   // B^PW
            const bool inc0 = (chunk == 1);              // window starts at t=0
            const float4* wp = x + ((size_t)b * T + (t0 - W_eff + seg * PW)) * C4 + cgg;
            float4 c = make_float4(0.f, 0.f, 0.f, 0.f);
            #pragma unroll 4
            for (int i = 0; i < PW; ++i) {
                float4 w = __ldg(wp + (size_t)i * C4);
                float a0 = (inc0 && seg == 0 && i == 0) ? 1.0f : A;
                c.x = fmaf(Bc, c.x, a0 * w.x);
                c.y = fmaf(Bc, c.y, a0 * w.y);
                c.z = fmaf(Bc, c.z, a0 * w.z);
                c.w = fmaf(Bc, c.w, a0 * w.w);
            }
            s_segL[seg][cg] = c;
            __syncthreads();
            if (seg == 0) {
                float4 cc = make_float4(0.f, 0.f, 0.f, 0.f);
                #pragma unroll
                for (int s = 0; s < SEGS; ++s)
                    cc = fma4(cB, cc, s_segL[s][cg]);
                s_cin[cg] = cc;
            }
            __syncthreads();
            cin = s_cin[cg];
        }
    }

    // ---- publish our chunk carry ASAP (keeps the chain moving) ----
    if (chunk < NCHUNK - 1 && seg == SEGS - 1) {
        g_carry[chain][chunk][cg] = fma4(B64, cin, s_pref[SEGS][cg]);
    }
    __syncthreads();
    if (tid == 0) {
        if (chunk < NCHUNK - 1) {
            __threadfence();
            asm volatile("st.release.gpu.u32 [%0], %1;"
                         :: "l"(&g_flags[chain][chunk]), "r"(1u) : "memory");
        }
        if (chunk > 0) g_flags[chain][chunk - 1] = 0;   // reset for next replay
    }

    // ---- finalize: out[t] = local[t] + B^(t+1) * seg_carry ----
    const float4 cs = fma4(B8S[seg], cin, s_pref[seg][cg]);

    float4* op = out + gbase;
    #pragma unroll
    for (int i = 0; i < PSTEPS; ++i) {
        __stcs(op + (size_t)i * C4, fma4(BPOW[i], cs, v[i]));
    }
}

extern "C" void kernel_launch(void* const* d_in, const int* in_sizes, int n_in,
                              void* d_out, int out_size)
{
    const float4* x = (const float4*)d_in[0];
    float4* out = (float4*)d_out;
    dim3 grid(NCHAIN, NCHUNK);   // chunk = slow dim -> predecessors get lower bids
    ema_chain_kernel<<<grid, 512>>>(x, out);
}